// round 13
// baseline (speedup 1.0000x reference)
#include <cuda_runtime.h>
#include <cuda_bf16.h>
#include <cuda_fp16.h>
#include <cstdint>
#include <math.h>

// ---------------------------------------------------------------------------
// Problem constants
// ---------------------------------------------------------------------------
#define EMB   1024
#define HID   4096
#define BATCH 2
#define SEQT  4096
#define MROWS (BATCH * SEQT)   // 8192
#define EPS_F 1e-6f
#define NCHUNK 32
#define CHUNK  (SEQT / NCHUNK)   // 128  (== BM, tiles are chunk-aligned)

// ---------------------------------------------------------------------------
// Scratch buffers (static; runtime allocation forbidden)
// ---------------------------------------------------------------------------
__device__ __align__(16) __half g_rh  [(size_t)MROWS * EMB];          //  16 MB
__device__ __align__(16) __half g_w12h[(size_t)(2 * HID) * EMB];      //  16 MB
__device__ __align__(16) __half g_w3h [(size_t)EMB * HID];            //   8 MB
__device__ __align__(16) __half g_ea  [(size_t)MROWS * HID];          //  64 MB exp(a)
__device__ __align__(16) __half g_eb  [(size_t)MROWS * HID];          //  64 MB exp(b)
__device__ __align__(16) __half g_y   [(size_t)MROWS * HID];          //  64 MB y=(sa*sb)/t^2
__device__ __align__(16) float g_pa[(size_t)BATCH * NCHUNK * HID];    //   1 MB
__device__ __align__(16) float g_pb[(size_t)BATCH * NCHUNK * HID];    //   1 MB
__device__ __align__(16) float g_scale[MROWS];                        //  32 KB rmsnorm scales

// ---------------------------------------------------------------------------
// PTX helpers (plain sm_103-legal)
// ---------------------------------------------------------------------------
__device__ __forceinline__ uint32_t smem_u32(const void* p) {
    uint32_t a;
    asm("{ .reg .u64 t; cvta.to.shared.u64 t, %1; cvt.u32.u64 %0, t; }"
        : "=r"(a) : "l"(p));
    return a;
}
__device__ __forceinline__ void cp16(uint32_t s, const void* g) {
    asm volatile("cp.async.cg.shared.global [%0], [%1], 16;" :: "r"(s), "l"(g));
}
__device__ __forceinline__ void cp_commit() {
    asm volatile("cp.async.commit_group;" ::: "memory");
}
__device__ __forceinline__ void ldsm_x4(uint32_t& r0, uint32_t& r1,
                                        uint32_t& r2, uint32_t& r3, uint32_t addr) {
    asm volatile("ldmatrix.sync.aligned.m8n8.x4.shared.b16 {%0,%1,%2,%3}, [%4];"
                 : "=r"(r0), "=r"(r1), "=r"(r2), "=r"(r3) : "r"(addr));
}
__device__ __forceinline__ void mma16(float& d0, float& d1, float& d2, float& d3,
                                      uint32_t a0, uint32_t a1, uint32_t a2, uint32_t a3,
                                      uint32_t b0, uint32_t b1) {
    asm volatile(
        "mma.sync.aligned.m16n8k16.row.col.f32.f16.f16.f32 "
        "{%0,%1,%2,%3}, {%4,%5,%6,%7}, {%8,%9}, {%0,%1,%2,%3};"
        : "+f"(d0), "+f"(d1), "+f"(d2), "+f"(d3)
        : "r"(a0), "r"(a1), "r"(a2), "r"(a3), "r"(b0), "r"(b1));
}

// ---------------------------------------------------------------------------
// fp16 NT GEMM (HMMA), 128x128x64 tiles, 3-stage cp.async, 256 thr, 2 CTA/SM.
// MODE 1: epilogue applies exp(), stores fp16 E0/E1 and per-chunk column sums.
// MODE 2: epilogue stores fp32 C0 = Cadd + S[m]*acc  (row-scaled residual).
// ---------------------------------------------------------------------------
#define BM 128
#define BN 128
#define BK 64
#define OPB 16384
#define STAGE_BYTES (2 * OPB)
#define NSTAGE 3
#define GEMM_SMEM (NSTAGE * STAGE_BYTES)

__device__ __forceinline__ uint32_t sw128(uint32_t off) {
    return off ^ ((off >> 3) & 0x70);
}

__device__ __forceinline__ void issue_tile_loads(
    uint32_t sbase, int st, const __half* Ab, const __half* Bb,
    int koff, int K, int tid)
{
    uint32_t stage = sbase + (uint32_t)st * STAGE_BYTES;
#pragma unroll
    for (int t = 0; t < 4; t++) {
        int idx = tid + t * 256;
        int row = idx >> 3;
        int u   = idx & 7;
        uint32_t sw = sw128((uint32_t)idx << 4);
        cp16(stage       + sw, Ab + (size_t)row * K + koff + u * 8);
        cp16(stage + OPB + sw, Bb + (size_t)row * K + koff + u * 8);
    }
}

template <int MODE>
__global__ void __launch_bounds__(256, 2)
hgemm_kernel(const __half* __restrict__ A, const __half* __restrict__ B,
             float* __restrict__ C0,
             const float* __restrict__ Cadd,
             __half* __restrict__ E0, __half* __restrict__ E1,
             float* __restrict__ pa, float* __restrict__ pb,
             const float* __restrict__ S,
             int M, int N, int K, int nsplit)
{
    extern __shared__ char smem[];
    uint32_t sbase = smem_u32(smem);
    const int tid  = threadIdx.x;
    const int wid  = tid >> 5;
    const int lane = tid & 31;
    const int wm   = wid & 1;
    const int wn   = wid >> 1;
    const int bm   = blockIdx.y * BM;
    const int bn   = blockIdx.x * BN;
    const int NC   = K / BK;

    const __half* Ab = A + (size_t)bm * K;
    const __half* Bb = B + (size_t)bn * K;

    float acc[4][4][4];
#pragma unroll
    for (int i = 0; i < 4; i++)
#pragma unroll
        for (int j = 0; j < 4; j++)
#pragma unroll
            for (int q = 0; q < 4; q++) acc[i][j][q] = 0.0f;

    const int a_m  = wm * 64 + (lane & 15);
    const int a_ku = lane >> 4;
    const int b_n  = wn * 32 + (lane & 7) + ((lane >> 4) << 3);
    const int b_ku = (lane >> 3) & 1;

    issue_tile_loads(sbase, 0, Ab, Bb, 0,  K, tid); cp_commit();
    issue_tile_loads(sbase, 1, Ab, Bb, BK, K, tid); cp_commit();

    for (int c = 0; c < NC; c++) {
        if (c + 1 < NC) asm volatile("cp.async.wait_group 1;" ::: "memory");
        else            asm volatile("cp.async.wait_group 0;" ::: "memory");
        __syncthreads();

        if (c + 2 < NC) {
            issue_tile_loads(sbase, (c + 2) % NSTAGE, Ab, Bb, (c + 2) * BK, K, tid);
            cp_commit();
        }

        uint32_t stage = sbase + (uint32_t)(c % NSTAGE) * STAGE_BYTES;
#pragma unroll
        for (int ks = 0; ks < 4; ks++) {
            uint32_t a0[4], a1[4], a2[4], a3[4];
            uint32_t bb0[2], bb1[2], bb2[2], bb3[2];
#pragma unroll
            for (int mf = 0; mf < 4; mf++) {
                int m  = a_m + mf * 16;
                int ku = ks * 2 + a_ku;
                ldsm_x4(a0[mf], a1[mf], a2[mf], a3[mf],
                        stage + sw128((uint32_t)(m * 128 + ku * 16)));
            }
#pragma unroll
            for (int nf2 = 0; nf2 < 2; nf2++) {
                int n  = b_n + nf2 * 16;
                int ku = ks * 2 + b_ku;
                uint32_t r0, r1, r2, r3;
                ldsm_x4(r0, r1, r2, r3,
                        stage + OPB + sw128((uint32_t)(n * 128 + ku * 16)));
                if (nf2 == 0) { bb0[0] = r0; bb0[1] = r1; bb1[0] = r2; bb1[1] = r3; }
                else          { bb2[0] = r0; bb2[1] = r1; bb3[0] = r2; bb3[1] = r3; }
            }
#pragma unroll
            for (int mf = 0; mf < 4; mf++) {
                mma16(acc[mf][0][0], acc[mf][0][1], acc[mf][0][2], acc[mf][0][3],
                      a0[mf], a1[mf], a2[mf], a3[mf], bb0[0], bb0[1]);
                mma16(acc[mf][1][0], acc[mf][1][1], acc[mf][1][2], acc[mf][1][3],
                      a0[mf], a1[mf], a2[mf], a3[mf], bb1[0], bb1[1]);
                mma16(acc[mf][2][0], acc[mf][2][1], acc[mf][2][2], acc[mf][2][3],
                      a0[mf], a1[mf], a2[mf], a3[mf], bb2[0], bb2[1]);
                mma16(acc[mf][3][0], acc[mf][3][1], acc[mf][3][2], acc[mf][3][3],
                      a0[mf], a1[mf], a2[mf], a3[mf], bb3[0], bb3[1]);
            }
        }
        __syncthreads();
    }

    const int inC0 = (bn < nsplit);
    const int ldc  = inC0 ? nsplit : (N - nsplit);
    const int cb   = inC0 ? bn : bn - nsplit;

    if (MODE == 2) {
#pragma unroll
        for (int mf = 0; mf < 4; mf++) {
            int r0 = bm + wm * 64 + mf * 16 + (lane >> 2);
            int r1 = r0 + 8;
            float s0 = S[r0], s1 = S[r1];
#pragma unroll
            for (int nf = 0; nf < 4; nf++) {
                int col = cb + wn * 32 + nf * 8 + (lane & 3) * 2;
                const float2 x0 = *(const float2*)(Cadd + (size_t)r0 * ldc + col);
                const float2 x1 = *(const float2*)(Cadd + (size_t)r1 * ldc + col);
                float2 v0 = make_float2(fmaf(s0, acc[mf][nf][0], x0.x),
                                        fmaf(s0, acc[mf][nf][1], x0.y));
                float2 v1 = make_float2(fmaf(s1, acc[mf][nf][2], x1.x),
                                        fmaf(s1, acc[mf][nf][3], x1.y));
                *(float2*)(C0 + (size_t)r0 * ldc + col) = v0;
                *(float2*)(C0 + (size_t)r1 * ldc + col) = v1;
            }
        }
    } else {
        // MODE 1: exp in place, store fp16, reduce per-chunk column sums
#pragma unroll
        for (int mf = 0; mf < 4; mf++)
#pragma unroll
            for (int nf = 0; nf < 4; nf++)
#pragma unroll
                for (int q = 0; q < 4; q++)
                    acc[mf][nf][q] = __expf(acc[mf][nf][q]);

        __half* Eb = inC0 ? E0 : E1;
#pragma unroll
        for (int mf = 0; mf < 4; mf++) {
            int r0 = bm + wm * 64 + mf * 16 + (lane >> 2);
            int r1 = r0 + 8;
#pragma unroll
            for (int nf = 0; nf < 4; nf++) {
                int col = cb + wn * 32 + nf * 8 + (lane & 3) * 2;
                *(__half2*)(Eb + (size_t)r0 * ldc + col) =
                    __floats2half2_rn(acc[mf][nf][0], acc[mf][nf][1]);
                *(__half2*)(Eb + (size_t)r1 * ldc + col) =
                    __floats2half2_rn(acc[mf][nf][2], acc[mf][nf][3]);
            }
        }

        float cs[4][2];
#pragma unroll
        for (int nf = 0; nf < 4; nf++) {
            cs[nf][0] = cs[nf][1] = 0.0f;
#pragma unroll
            for (int mf = 0; mf < 4; mf++) {
                cs[nf][0] += acc[mf][nf][0] + acc[mf][nf][2];
                cs[nf][1] += acc[mf][nf][1] + acc[mf][nf][3];
            }
#pragma unroll
            for (int off = 4; off < 32; off <<= 1) {
                cs[nf][0] += __shfl_xor_sync(0xffffffffu, cs[nf][0], off);
                cs[nf][1] += __shfl_xor_sync(0xffffffffu, cs[nf][1], off);
            }
        }
        float* red = (float*)smem;   // stages dead after last mainloop sync
        if (lane < 4) {
#pragma unroll
            for (int nf = 0; nf < 4; nf++) {
                int col = wn * 32 + nf * 8 + lane * 2;
                red[wm * BN + col]     = cs[nf][0];
                red[wm * BN + col + 1] = cs[nf][1];
            }
        }
        __syncthreads();
        if (tid < BN) {
            int bb = bm / SEQT;
            int ch = (bm % SEQT) / CHUNK;
            float* P = inC0 ? pa : pb;
            P[(size_t)(bb * NCHUNK + ch) * HID + cb + tid] =
                red[tid] + red[BN + tid];
        }
    }
}

// ---------------------------------------------------------------------------
// Block-wide sum reduce
// ---------------------------------------------------------------------------
__device__ __forceinline__ float block_reduce_sum(float v) {
    __shared__ float sh[32];
    int lane = threadIdx.x & 31;
    int wid  = threadIdx.x >> 5;
#pragma unroll
    for (int o = 16; o; o >>= 1) v += __shfl_xor_sync(0xffffffffu, v, o);
    if (lane == 0) sh[wid] = v;
    __syncthreads();
    int nw = blockDim.x >> 5;
    if (wid == 0) {
        v = (lane < nw) ? sh[lane] : 0.0f;
#pragma unroll
        for (int o = 16; o; o >>= 1) v += __shfl_xor_sync(0xffffffffu, v, o);
    }
    return v;
}

// ---------------------------------------------------------------------------
// RMSNorm fp32 -> fp16. One block per row.
// ---------------------------------------------------------------------------
__global__ void rmsnorm_f16_kernel(const float* __restrict__ in,
                                   __half* __restrict__ outp, int W) {
    int row = blockIdx.x;
    const float4* ir = (const float4*)(in + (size_t)row * W);
    int nvec = W >> 2;
    float ss = 0.0f;
    for (int i = threadIdx.x; i < nvec; i += 256) {
        float4 v = ir[i];
        ss += v.x * v.x + v.y * v.y + v.z * v.z + v.w * v.w;
    }
    ss = block_reduce_sum(ss);
    __shared__ float s_scale;
    if (threadIdx.x == 0) s_scale = rsqrtf(ss / (float)W + EPS_F);
    __syncthreads();
    float sc = s_scale;
    __half2* op = (__half2*)(outp + (size_t)row * W);
    for (int i = threadIdx.x; i < nvec; i += 256) {
        float4 v = ir[i];
        op[2 * i]     = __floats2half2_rn(v.x * sc, v.y * sc);
        op[2 * i + 1] = __floats2half2_rn(v.z * sc, v.w * sc);
    }
}

// ---------------------------------------------------------------------------
// Row rms-scale from fp16 y: scale[row] = rsqrt(mean(y^2) + eps)
// ---------------------------------------------------------------------------
__global__ void rowscale_kernel(const __half* __restrict__ y,
                                float* __restrict__ scale) {
    int row = blockIdx.x;
    const __half2* ir = (const __half2*)(y + (size_t)row * HID);
    float ss = 0.0f;
    for (int i = threadIdx.x; i < HID / 2; i += 256) {
        float2 v = __half22float2(ir[i]);
        ss += v.x * v.x + v.y * v.y;
    }
    ss = block_reduce_sum(ss);
    if (threadIdx.x == 0) scale[row] = rsqrtf(ss / (float)HID + EPS_F);
}

// ---------------------------------------------------------------------------
// Fused fp32 -> fp16 convert for W1, W2, W3 in one launch.
// ---------------------------------------------------------------------------
__global__ void wconv_all_kernel(const float* __restrict__ W1,
                                 const float* __restrict__ W2,
                                 const float* __restrict__ W3,
                                 __half* __restrict__ w12h,
                                 __half* __restrict__ w3h,
                                 int nv12, int nv3) {
    int i = blockIdx.x * blockDim.x + threadIdx.x;
    const float* src;
    __half2* dst;
    int j;
    if (i < nv12)                { src = W1; dst = (__half2*)w12h;                      j = i; }
    else if (i < 2 * nv12)       { src = W2; dst = (__half2*)(w12h + (size_t)nv12 * 4); j = i - nv12; }
    else if (i < 2 * nv12 + nv3) { src = W3; dst = (__half2*)w3h;                      j = i - 2 * nv12; }
    else return;
    float4 v = ((const float4*)src)[j];
    dst[2 * j]     = __floats2half2_rn(v.x, v.y);
    dst[2 * j + 1] = __floats2half2_rn(v.z, v.w);
}

// ---------------------------------------------------------------------------
// pass2: exclusive prefix over chunk sums. All 32 loads batched (MLP) before
// the register scan, then 32 stores.
// ---------------------------------------------------------------------------
__global__ void bar_pass2_kernel(float* __restrict__ pa,
                                 float* __restrict__ pb) {
    int idx = blockIdx.x * 256 + threadIdx.x;   // 0 .. BATCH*HID-1
    int bb = idx >> 12;
    int h  = idx & (HID - 1);
    float va[NCHUNK], vb[NCHUNK];
#pragma unroll
    for (int c = 0; c < NCHUNK; c++) {
        va[c] = pa[(size_t)(bb * NCHUNK + c) * HID + h];
        vb[c] = pb[(size_t)(bb * NCHUNK + c) * HID + h];
    }
    float ra = 0.0f, rb = 0.0f;
#pragma unroll
    for (int c = 0; c < NCHUNK; c++) {
        float ta = va[c], tb = vb[c];
        va[c] = ra; vb[c] = rb;
        ra += ta; rb += tb;
    }
#pragma unroll
    for (int c = 0; c < NCHUNK; c++) {
        pa[(size_t)(bb * NCHUNK + c) * HID + h] = va[c];
        pb[(size_t)(bb * NCHUNK + c) * HID + h] = vb[c];
    }
}

// ---------------------------------------------------------------------------
// pass3: within-chunk scan from prefix; reads fp16 ea/eb, writes fp16
// y = (sa*sb)/(t+1)^2  (the reference normalization keeps y in fp16 range).
// Each thread handles 2 adjacent channels.
// ---------------------------------------------------------------------------
__global__ void bar_pass3_kernel(const __half* __restrict__ ea,
                                 const __half* __restrict__ eb,
                                 const float* __restrict__ pa,
                                 const float* __restrict__ pb,
                                 __half* __restrict__ y) {
    int h2 = blockIdx.x * 256 + threadIdx.x;   // pair index, 0 .. HID/2-1
    int c  = blockIdx.y;
    int bb = blockIdx.z;
    size_t base = (size_t)bb * SEQT * HID + (size_t)c * CHUNK * HID + h2 * 2;
    const __half2* ap = (const __half2*)(ea + base);
    const __half2* bp = (const __half2*)(eb + base);
    __half2* yp = (__half2*)(y + base);

    int po = (bb * NCHUNK + c) * HID + h2 * 2;
    float sa0 = pa[po], sa1 = pa[po + 1];
    float sb0 = pb[po], sb1 = pb[po + 1];
#pragma unroll 4
    for (int t = 0; t < CHUNK; t++) {
        float2 va = __half22float2(ap[(size_t)t * (HID / 2)]);
        float2 vb = __half22float2(bp[(size_t)t * (HID / 2)]);
        sa0 += va.x; sa1 += va.y;
        sb0 += vb.x; sb1 += vb.y;
        float tf = (float)(c * CHUNK + t + 1);
        float inv = 1.0f / (tf * tf);
        yp[(size_t)t * (HID / 2)] =
            __floats2half2_rn(sa0 * sb0 * inv, sa1 * sb1 * inv);
    }
}

// ---------------------------------------------------------------------------
// kernel_launch
// ---------------------------------------------------------------------------
extern "C" void kernel_launch(void* const* d_in, const int* in_sizes, int n_in,
                              void* d_out, int out_size) {
    const float* x  = (const float*)d_in[0];
    const float* W1 = (const float*)d_in[1];
    const float* W2 = (const float*)d_in[2];
    const float* W3 = (const float*)d_in[3];
    float* out = (float*)d_out;

    __half *rh, *w12h, *w3h, *ea, *eb, *y_p;
    float *pa_p, *pb_p, *sc_p;
    cudaGetSymbolAddress((void**)&rh,   g_rh);
    cudaGetSymbolAddress((void**)&w12h, g_w12h);
    cudaGetSymbolAddress((void**)&w3h,  g_w3h);
    cudaGetSymbolAddress((void**)&ea,   g_ea);
    cudaGetSymbolAddress((void**)&eb,   g_eb);
    cudaGetSymbolAddress((void**)&y_p,  g_y);
    cudaGetSymbolAddress((void**)&pa_p, g_pa);
    cudaGetSymbolAddress((void**)&pb_p, g_pb);
    cudaGetSymbolAddress((void**)&sc_p, g_scale);

    cudaFuncSetAttribute(hgemm_kernel<1>, cudaFuncAttributeMaxDynamicSharedMemorySize,
                         GEMM_SMEM);
    cudaFuncSetAttribute(hgemm_kernel<2>, cudaFuncAttributeMaxDynamicSharedMemorySize,
                         GEMM_SMEM);

    // Weight converts, one launch
    {
        int nv12 = (HID * EMB) / 4;
        int nv3  = (EMB * HID) / 4;
        int tot  = 2 * nv12 + nv3;
        wconv_all_kernel<<<(tot + 255) / 256, 256>>>(W1, W2, W3, w12h, w3h, nv12, nv3);
    }

    // 1) r = rmsnorm(x) -> fp16
    rmsnorm_f16_kernel<<<MROWS, 256>>>(x, rh, EMB);

    // 2) fused GEMM1/2 + exp + chunk sums: ea,eb fp16 + pa,pb partials
    hgemm_kernel<1><<<dim3((2 * HID) / BN, MROWS / BM), 256, GEMM_SMEM>>>(
        rh, w12h, nullptr, nullptr, ea, eb, pa_p, pb_p, nullptr,
        MROWS, 2 * HID, EMB, HID);

    // 3) prefix over chunks, then within-chunk scan -> y fp16 (with 1/t^2)
    bar_pass2_kernel<<<(BATCH * HID) / 256, 256>>>(pa_p, pb_p);
    {
        dim3 grid(HID / 512, NCHUNK, BATCH);
        bar_pass3_kernel<<<grid, 256>>>(ea, eb, pa_p, pb_p, y_p);
    }

    // 4) per-row rms scales from y
    rowscale_kernel<<<MROWS, 256>>>(y_p, sc_p);

    // 5) out = x + scale[m] * (y @ W3^T)
    hgemm_kernel<2><<<dim3(EMB / BN, MROWS / BM), 256, GEMM_SMEM>>>(
        y_p, w3h, out, x, nullptr, nullptr, nullptr, nullptr, sc_p,
        MROWS, EMB, HID, EMB);
}

// round 14
// speedup vs baseline: 1.0263x; 1.0263x over previous
#include <cuda_runtime.h>
#include <cuda_bf16.h>
#include <cuda_fp16.h>
#include <cstdint>
#include <math.h>

// ---------------------------------------------------------------------------
// Problem constants
// ---------------------------------------------------------------------------
#define EMB   1024
#define HID   4096
#define BATCH 2
#define SEQT  4096
#define MROWS (BATCH * SEQT)   // 8192
#define EPS_F 1e-6f
#define NCHUNK 32
#define CHUNK  (SEQT / NCHUNK)   // 128  (== M-tile, chunk-aligned)

// ---------------------------------------------------------------------------
// Scratch buffers (static; runtime allocation forbidden)
// ---------------------------------------------------------------------------
__device__ __align__(16) __half g_rh  [(size_t)MROWS * EMB];          //  16 MB
__device__ __align__(16) __half g_w12h[(size_t)(2 * HID) * EMB];      //  16 MB
__device__ __align__(16) __half g_w3h [(size_t)EMB * HID];            //   8 MB
__device__ __align__(16) __half g_ea  [(size_t)MROWS * HID];          //  64 MB exp(a)
__device__ __align__(16) __half g_eb  [(size_t)MROWS * HID];          //  64 MB exp(b)
__device__ __align__(16) __half g_y   [(size_t)MROWS * HID];          //  64 MB y=(sa*sb)/t^2
__device__ __align__(16) float g_pa[(size_t)BATCH * NCHUNK * HID];    //   1 MB
__device__ __align__(16) float g_pb[(size_t)BATCH * NCHUNK * HID];    //   1 MB
__device__ __align__(16) float g_ss[(size_t)MROWS * 8];               // 256 KB  y^2 row partials

// ---------------------------------------------------------------------------
// PTX helpers (plain sm_103-legal)
// ---------------------------------------------------------------------------
__device__ __forceinline__ uint32_t smem_u32(const void* p) {
    uint32_t a;
    asm("{ .reg .u64 t; cvta.to.shared.u64 t, %1; cvt.u32.u64 %0, t; }"
        : "=r"(a) : "l"(p));
    return a;
}
__device__ __forceinline__ void cp16(uint32_t s, const void* g) {
    asm volatile("cp.async.cg.shared.global [%0], [%1], 16;" :: "r"(s), "l"(g));
}
__device__ __forceinline__ void cp_commit() {
    asm volatile("cp.async.commit_group;" ::: "memory");
}
__device__ __forceinline__ void ldsm_x4(uint32_t& r0, uint32_t& r1,
                                        uint32_t& r2, uint32_t& r3, uint32_t addr) {
    asm volatile("ldmatrix.sync.aligned.m8n8.x4.shared.b16 {%0,%1,%2,%3}, [%4];"
                 : "=r"(r0), "=r"(r1), "=r"(r2), "=r"(r3) : "r"(addr));
}
__device__ __forceinline__ void mma16(float& d0, float& d1, float& d2, float& d3,
                                      uint32_t a0, uint32_t a1, uint32_t a2, uint32_t a3,
                                      uint32_t b0, uint32_t b1) {
    asm volatile(
        "mma.sync.aligned.m16n8k16.row.col.f32.f16.f16.f32 "
        "{%0,%1,%2,%3}, {%4,%5,%6,%7}, {%8,%9}, {%0,%1,%2,%3};"
        : "+f"(d0), "+f"(d1), "+f"(d2), "+f"(d3)
        : "r"(a0), "r"(a1), "r"(a2), "r"(a3), "r"(b0), "r"(b1));
}
__device__ __forceinline__ uint32_t sw128(uint32_t off) {
    return off ^ ((off >> 3) & 0x70);
}

// ===========================================================================
// GEMM A (fused fc1/fc2): 128x256x64 tiles, 512 threads, 3-stage, 1 CTA/SM.
// Epilogue: exp() -> fp16 E0/E1 (split at nsplit) + per-chunk column sums.
// ===========================================================================
#define BK 64
#define APB 16384                 // A tile bytes (128 x 128B)
#define BPB 32768                 // B tile bytes (256 x 128B)
#define STG2 (APB + BPB)          // 48 KB
#define NST2 3
#define SMEM2 (NST2 * STG2)       // 144 KB

__device__ __forceinline__ void loads2(
    uint32_t sbase, int st, const __half* Ab, const __half* Bb,
    int koff, int K, int tid)
{
    uint32_t stage = sbase + (uint32_t)st * STG2;
#pragma unroll
    for (int t = 0; t < 2; t++) {               // A: 1024 16B units
        int idx = tid + t * 512;
        int row = idx >> 3, u = idx & 7;
        cp16(stage + sw128((uint32_t)idx << 4), Ab + (size_t)row * K + koff + u * 8);
    }
#pragma unroll
    for (int t = 0; t < 4; t++) {               // B: 2048 16B units
        int idx = tid + t * 512;
        int row = idx >> 3, u = idx & 7;
        cp16(stage + APB + sw128((uint32_t)idx << 4), Bb + (size_t)row * K + koff + u * 8);
    }
}

__global__ void __launch_bounds__(512, 1)
hgemm_exp_kernel(const __half* __restrict__ A, const __half* __restrict__ B,
                 __half* __restrict__ E0, __half* __restrict__ E1,
                 float* __restrict__ pa, float* __restrict__ pb,
                 int M, int N, int K, int nsplit)
{
    extern __shared__ char smem[];
    uint32_t sbase = smem_u32(smem);
    const int tid  = threadIdx.x;
    const int wid  = tid >> 5;
    const int lane = tid & 31;
    const int wm   = wid & 1;        // 2 warps in m (64 rows each)
    const int wn   = wid >> 1;       // 8 warps in n (32 cols each)
    const int bm   = blockIdx.y * 128;
    const int bn   = blockIdx.x * 256;
    const int NC   = K / BK;

    const __half* Ab = A + (size_t)bm * K;
    const __half* Bb = B + (size_t)bn * K;

    float acc[4][4][4];
#pragma unroll
    for (int i = 0; i < 4; i++)
#pragma unroll
        for (int j = 0; j < 4; j++)
#pragma unroll
            for (int q = 0; q < 4; q++) acc[i][j][q] = 0.0f;

    const int a_m  = wm * 64 + (lane & 15);
    const int a_ku = lane >> 4;
    const int b_n  = wn * 32 + (lane & 7) + ((lane >> 4) << 3);
    const int b_ku = (lane >> 3) & 1;

    loads2(sbase, 0, Ab, Bb, 0,  K, tid); cp_commit();
    loads2(sbase, 1, Ab, Bb, BK, K, tid); cp_commit();

    for (int c = 0; c < NC; c++) {
        if (c + 1 < NC) asm volatile("cp.async.wait_group 1;" ::: "memory");
        else            asm volatile("cp.async.wait_group 0;" ::: "memory");
        __syncthreads();

        if (c + 2 < NC) {
            loads2(sbase, (c + 2) % NST2, Ab, Bb, (c + 2) * BK, K, tid);
            cp_commit();
        }

        uint32_t stage = sbase + (uint32_t)(c % NST2) * STG2;
#pragma unroll
        for (int ks = 0; ks < 4; ks++) {
            uint32_t a0[4], a1[4], a2[4], a3[4];
            uint32_t bb0[2], bb1[2], bb2[2], bb3[2];
#pragma unroll
            for (int mf = 0; mf < 4; mf++) {
                int m  = a_m + mf * 16;
                int ku = ks * 2 + a_ku;
                ldsm_x4(a0[mf], a1[mf], a2[mf], a3[mf],
                        stage + sw128((uint32_t)(m * 128 + ku * 16)));
            }
#pragma unroll
            for (int nf2 = 0; nf2 < 2; nf2++) {
                int n  = b_n + nf2 * 16;
                int ku = ks * 2 + b_ku;
                uint32_t r0, r1, r2, r3;
                ldsm_x4(r0, r1, r2, r3,
                        stage + APB + sw128((uint32_t)(n * 128 + ku * 16)));
                if (nf2 == 0) { bb0[0] = r0; bb0[1] = r1; bb1[0] = r2; bb1[1] = r3; }
                else          { bb2[0] = r0; bb2[1] = r1; bb3[0] = r2; bb3[1] = r3; }
            }
#pragma unroll
            for (int mf = 0; mf < 4; mf++) {
                mma16(acc[mf][0][0], acc[mf][0][1], acc[mf][0][2], acc[mf][0][3],
                      a0[mf], a1[mf], a2[mf], a3[mf], bb0[0], bb0[1]);
                mma16(acc[mf][1][0], acc[mf][1][1], acc[mf][1][2], acc[mf][1][3],
                      a0[mf], a1[mf], a2[mf], a3[mf], bb1[0], bb1[1]);
                mma16(acc[mf][2][0], acc[mf][2][1], acc[mf][2][2], acc[mf][2][3],
                      a0[mf], a1[mf], a2[mf], a3[mf], bb2[0], bb2[1]);
                mma16(acc[mf][3][0], acc[mf][3][1], acc[mf][3][2], acc[mf][3][3],
                      a0[mf], a1[mf], a2[mf], a3[mf], bb3[0], bb3[1]);
            }
        }
        __syncthreads();
    }

    const int inC0 = (bn < nsplit);
    const int ldc  = inC0 ? nsplit : (N - nsplit);
    const int cb   = inC0 ? bn : bn - nsplit;

    // exp in place
#pragma unroll
    for (int mf = 0; mf < 4; mf++)
#pragma unroll
        for (int nf = 0; nf < 4; nf++)
#pragma unroll
            for (int q = 0; q < 4; q++)
                acc[mf][nf][q] = __expf(acc[mf][nf][q]);

    __half* Eb = inC0 ? E0 : E1;
#pragma unroll
    for (int mf = 0; mf < 4; mf++) {
        int r0 = bm + wm * 64 + mf * 16 + (lane >> 2);
        int r1 = r0 + 8;
#pragma unroll
        for (int nf = 0; nf < 4; nf++) {
            int col = cb + wn * 32 + nf * 8 + (lane & 3) * 2;
            *(__half2*)(Eb + (size_t)r0 * ldc + col) =
                __floats2half2_rn(acc[mf][nf][0], acc[mf][nf][1]);
            *(__half2*)(Eb + (size_t)r1 * ldc + col) =
                __floats2half2_rn(acc[mf][nf][2], acc[mf][nf][3]);
        }
    }

    // per-column sums over the tile's 128 rows -> chunk partials
    float cs[4][2];
#pragma unroll
    for (int nf = 0; nf < 4; nf++) {
        cs[nf][0] = cs[nf][1] = 0.0f;
#pragma unroll
        for (int mf = 0; mf < 4; mf++) {
            cs[nf][0] += acc[mf][nf][0] + acc[mf][nf][2];
            cs[nf][1] += acc[mf][nf][1] + acc[mf][nf][3];
        }
#pragma unroll
        for (int off = 4; off < 32; off <<= 1) {
            cs[nf][0] += __shfl_xor_sync(0xffffffffu, cs[nf][0], off);
            cs[nf][1] += __shfl_xor_sync(0xffffffffu, cs[nf][1], off);
        }
    }
    float* red = (float*)smem;   // stages dead after final sync
    if (lane < 4) {
#pragma unroll
        for (int nf = 0; nf < 4; nf++) {
            int col = wn * 32 + nf * 8 + lane * 2;
            red[wm * 256 + col]     = cs[nf][0];
            red[wm * 256 + col + 1] = cs[nf][1];
        }
    }
    __syncthreads();
    if (tid < 256) {
        int bb = bm / SEQT;
        int ch = (bm % SEQT) / CHUNK;
        float* P = inC0 ? pa : pb;
        P[(size_t)(bb * NCHUNK + ch) * HID + cb + tid] = red[tid] + red[256 + tid];
    }
}

// ===========================================================================
// GEMM B (fc3): 128x128x64 tiles, 256 threads, 2 CTA/SM.
// Epilogue: out = Cadd + S[m]*acc, where S[m] = rsqrt(mean(y[m]^2)+eps)
// computed from 8 per-row partials in SS.
// ===========================================================================
#define OPB 16384
#define STG1 (2 * OPB)
#define NST1 3
#define SMEM1 (NST1 * STG1)

__device__ __forceinline__ void loads1(
    uint32_t sbase, int st, const __half* Ab, const __half* Bb,
    int koff, int K, int tid)
{
    uint32_t stage = sbase + (uint32_t)st * STG1;
#pragma unroll
    for (int t = 0; t < 4; t++) {
        int idx = tid + t * 256;
        int row = idx >> 3, u = idx & 7;
        uint32_t sw = sw128((uint32_t)idx << 4);
        cp16(stage       + sw, Ab + (size_t)row * K + koff + u * 8);
        cp16(stage + OPB + sw, Bb + (size_t)row * K + koff + u * 8);
    }
}

__global__ void __launch_bounds__(256, 2)
hgemm_scaled_kernel(const __half* __restrict__ A, const __half* __restrict__ B,
                    float* __restrict__ C, const float* __restrict__ Cadd,
                    const float* __restrict__ SS,
                    int M, int N, int K)
{
    extern __shared__ char smem[];
    uint32_t sbase = smem_u32(smem);
    const int tid  = threadIdx.x;
    const int wid  = tid >> 5;
    const int lane = tid & 31;
    const int wm   = wid & 1;
    const int wn   = wid >> 1;
    const int bm   = blockIdx.y * 128;
    const int bn   = blockIdx.x * 128;
    const int NC   = K / BK;

    const __half* Ab = A + (size_t)bm * K;
    const __half* Bb = B + (size_t)bn * K;

    float acc[4][4][4];
#pragma unroll
    for (int i = 0; i < 4; i++)
#pragma unroll
        for (int j = 0; j < 4; j++)
#pragma unroll
            for (int q = 0; q < 4; q++) acc[i][j][q] = 0.0f;

    const int a_m  = wm * 64 + (lane & 15);
    const int a_ku = lane >> 4;
    const int b_n  = wn * 32 + (lane & 7) + ((lane >> 4) << 3);
    const int b_ku = (lane >> 3) & 1;

    loads1(sbase, 0, Ab, Bb, 0,  K, tid); cp_commit();
    loads1(sbase, 1, Ab, Bb, BK, K, tid); cp_commit();

    for (int c = 0; c < NC; c++) {
        if (c + 1 < NC) asm volatile("cp.async.wait_group 1;" ::: "memory");
        else            asm volatile("cp.async.wait_group 0;" ::: "memory");
        __syncthreads();

        if (c + 2 < NC) {
            loads1(sbase, (c + 2) % NST1, Ab, Bb, (c + 2) * BK, K, tid);
            cp_commit();
        }

        uint32_t stage = sbase + (uint32_t)(c % NST1) * STG1;
#pragma unroll
        for (int ks = 0; ks < 4; ks++) {
            uint32_t a0[4], a1[4], a2[4], a3[4];
            uint32_t bb0[2], bb1[2], bb2[2], bb3[2];
#pragma unroll
            for (int mf = 0; mf < 4; mf++) {
                int m  = a_m + mf * 16;
                int ku = ks * 2 + a_ku;
                ldsm_x4(a0[mf], a1[mf], a2[mf], a3[mf],
                        stage + sw128((uint32_t)(m * 128 + ku * 16)));
            }
#pragma unroll
            for (int nf2 = 0; nf2 < 2; nf2++) {
                int n  = b_n + nf2 * 16;
                int ku = ks * 2 + b_ku;
                uint32_t r0, r1, r2, r3;
                ldsm_x4(r0, r1, r2, r3,
                        stage + OPB + sw128((uint32_t)(n * 128 + ku * 16)));
                if (nf2 == 0) { bb0[0] = r0; bb0[1] = r1; bb1[0] = r2; bb1[1] = r3; }
                else          { bb2[0] = r0; bb2[1] = r1; bb3[0] = r2; bb3[1] = r3; }
            }
#pragma unroll
            for (int mf = 0; mf < 4; mf++) {
                mma16(acc[mf][0][0], acc[mf][0][1], acc[mf][0][2], acc[mf][0][3],
                      a0[mf], a1[mf], a2[mf], a3[mf], bb0[0], bb0[1]);
                mma16(acc[mf][1][0], acc[mf][1][1], acc[mf][1][2], acc[mf][1][3],
                      a0[mf], a1[mf], a2[mf], a3[mf], bb1[0], bb1[1]);
                mma16(acc[mf][2][0], acc[mf][2][1], acc[mf][2][2], acc[mf][2][3],
                      a0[mf], a1[mf], a2[mf], a3[mf], bb2[0], bb2[1]);
                mma16(acc[mf][3][0], acc[mf][3][1], acc[mf][3][2], acc[mf][3][3],
                      a0[mf], a1[mf], a2[mf], a3[mf], bb3[0], bb3[1]);
            }
        }
        __syncthreads();
    }

    // Row scales from partials (smem aliases dead stages)
    float* Ssm = (float*)smem;
    if (tid < 128) {
        const float* ps = SS + (size_t)(bm + tid) * 8;
        float s = ps[0] + ps[1] + ps[2] + ps[3] + ps[4] + ps[5] + ps[6] + ps[7];
        Ssm[tid] = rsqrtf(s * (1.0f / (float)HID) + EPS_F);
    }
    __syncthreads();

#pragma unroll
    for (int mf = 0; mf < 4; mf++) {
        int r0 = bm + wm * 64 + mf * 16 + (lane >> 2);
        int r1 = r0 + 8;
        float s0 = Ssm[r0 - bm], s1 = Ssm[r1 - bm];
#pragma unroll
        for (int nf = 0; nf < 4; nf++) {
            int col = bn + wn * 32 + nf * 8 + (lane & 3) * 2;
            const float2 x0 = *(const float2*)(Cadd + (size_t)r0 * N + col);
            const float2 x1 = *(const float2*)(Cadd + (size_t)r1 * N + col);
            float2 v0 = make_float2(fmaf(s0, acc[mf][nf][0], x0.x),
                                    fmaf(s0, acc[mf][nf][1], x0.y));
            float2 v1 = make_float2(fmaf(s1, acc[mf][nf][2], x1.x),
                                    fmaf(s1, acc[mf][nf][3], x1.y));
            *(float2*)(C + (size_t)r0 * N + col) = v0;
            *(float2*)(C + (size_t)r1 * N + col) = v1;
        }
    }
}

// ---------------------------------------------------------------------------
// Block-wide sum reduce
// ---------------------------------------------------------------------------
__device__ __forceinline__ float block_reduce_sum(float v) {
    __shared__ float sh[32];
    int lane = threadIdx.x & 31;
    int wid  = threadIdx.x >> 5;
#pragma unroll
    for (int o = 16; o; o >>= 1) v += __shfl_xor_sync(0xffffffffu, v, o);
    if (lane == 0) sh[wid] = v;
    __syncthreads();
    int nw = blockDim.x >> 5;
    if (wid == 0) {
        v = (lane < nw) ? sh[lane] : 0.0f;
#pragma unroll
        for (int o = 16; o; o >>= 1) v += __shfl_xor_sync(0xffffffffu, v, o);
    }
    return v;
}

// ---------------------------------------------------------------------------
// RMSNorm fp32 -> fp16. One block per row.
// ---------------------------------------------------------------------------
__global__ void rmsnorm_f16_kernel(const float* __restrict__ in,
                                   __half* __restrict__ outp, int W) {
    int row = blockIdx.x;
    const float4* ir = (const float4*)(in + (size_t)row * W);
    int nvec = W >> 2;
    float ss = 0.0f;
    for (int i = threadIdx.x; i < nvec; i += 256) {
        float4 v = ir[i];
        ss += v.x * v.x + v.y * v.y + v.z * v.z + v.w * v.w;
    }
    ss = block_reduce_sum(ss);
    __shared__ float s_scale;
    if (threadIdx.x == 0) s_scale = rsqrtf(ss / (float)W + EPS_F);
    __syncthreads();
    float sc = s_scale;
    __half2* op = (__half2*)(outp + (size_t)row * W);
    for (int i = threadIdx.x; i < nvec; i += 256) {
        float4 v = ir[i];
        op[2 * i]     = __floats2half2_rn(v.x * sc, v.y * sc);
        op[2 * i + 1] = __floats2half2_rn(v.z * sc, v.w * sc);
    }
}

// ---------------------------------------------------------------------------
// Fused fp32 -> fp16 convert for W1, W2, W3 in one launch.
// ---------------------------------------------------------------------------
__global__ void wconv_all_kernel(const float* __restrict__ W1,
                                 const float* __restrict__ W2,
                                 const float* __restrict__ W3,
                                 __half* __restrict__ w12h,
                                 __half* __restrict__ w3h,
                                 int nv12, int nv3) {
    int i = blockIdx.x * blockDim.x + threadIdx.x;
    const float* src;
    __half2* dst;
    int j;
    if (i < nv12)                { src = W1; dst = (__half2*)w12h;                      j = i; }
    else if (i < 2 * nv12)       { src = W2; dst = (__half2*)(w12h + (size_t)nv12 * 4); j = i - nv12; }
    else if (i < 2 * nv12 + nv3) { src = W3; dst = (__half2*)w3h;                      j = i - 2 * nv12; }
    else return;
    float4 v = ((const float4*)src)[j];
    dst[2 * j]     = __floats2half2_rn(v.x, v.y);
    dst[2 * j + 1] = __floats2half2_rn(v.z, v.w);
}

// ---------------------------------------------------------------------------
// pass2: exclusive prefix over chunk sums (batched loads for MLP)
// ---------------------------------------------------------------------------
__global__ void bar_pass2_kernel(float* __restrict__ pa,
                                 float* __restrict__ pb) {
    int idx = blockIdx.x * 256 + threadIdx.x;
    int bb = idx >> 12;
    int h  = idx & (HID - 1);
    float va[NCHUNK], vb[NCHUNK];
#pragma unroll
    for (int c = 0; c < NCHUNK; c++) {
        va[c] = pa[(size_t)(bb * NCHUNK + c) * HID + h];
        vb[c] = pb[(size_t)(bb * NCHUNK + c) * HID + h];
    }
    float ra = 0.0f, rb = 0.0f;
#pragma unroll
    for (int c = 0; c < NCHUNK; c++) {
        float ta = va[c], tb = vb[c];
        va[c] = ra; vb[c] = rb;
        ra += ta; rb += tb;
    }
#pragma unroll
    for (int c = 0; c < NCHUNK; c++) {
        pa[(size_t)(bb * NCHUNK + c) * HID + h] = va[c];
        pb[(size_t)(bb * NCHUNK + c) * HID + h] = vb[c];
    }
}

// ---------------------------------------------------------------------------
// pass3: within-chunk scan; y = (sa*sb)/(t+1)^2 in fp16; also emits per-row
// partial sums of y^2 (8 partials per row, one per blockIdx.x) for fc3's
// fused rmsnorm scale.
// ---------------------------------------------------------------------------
__global__ void bar_pass3_kernel(const __half* __restrict__ ea,
                                 const __half* __restrict__ eb,
                                 const float* __restrict__ pa,
                                 const float* __restrict__ pb,
                                 __half* __restrict__ y,
                                 float* __restrict__ ss) {
    __shared__ float wsum[8][CHUNK];
    int tid = threadIdx.x;
    int wid = tid >> 5, lane = tid & 31;
    int h2 = blockIdx.x * 256 + tid;           // pair index
    int c  = blockIdx.y;
    int bb = blockIdx.z;
    size_t base = (size_t)bb * SEQT * HID + (size_t)c * CHUNK * HID + h2 * 2;
    const __half2* ap = (const __half2*)(ea + base);
    const __half2* bp = (const __half2*)(eb + base);
    __half2* yp = (__half2*)(y + base);

    int po = (bb * NCHUNK + c) * HID + h2 * 2;
    float sa0 = pa[po], sa1 = pa[po + 1];
    float sb0 = pb[po], sb1 = pb[po + 1];
#pragma unroll 4
    for (int t = 0; t < CHUNK; t++) {
        float2 va = __half22float2(ap[(size_t)t * (HID / 2)]);
        float2 vb = __half22float2(bp[(size_t)t * (HID / 2)]);
        sa0 += va.x; sa1 += va.y;
        sb0 += vb.x; sb1 += vb.y;
        float tf = (float)(c * CHUNK + t + 1);
        float inv = __fdividef(1.0f, tf * tf);
        float y0 = sa0 * sb0 * inv;
        float y1 = sa1 * sb1 * inv;
        yp[(size_t)t * (HID / 2)] = __floats2half2_rn(y0, y1);
        float q = y0 * y0 + y1 * y1;
#pragma unroll
        for (int off = 16; off; off >>= 1)
            q += __shfl_xor_sync(0xffffffffu, q, off);
        if (lane == 0) wsum[wid][t] = q;
    }
    __syncthreads();
    if (tid < CHUNK) {
        float s = 0.0f;
#pragma unroll
        for (int w = 0; w < 8; w++) s += wsum[w][tid];
        int row = bb * SEQT + c * CHUNK + tid;
        ss[(size_t)row * 8 + blockIdx.x] = s;
    }
}

// ---------------------------------------------------------------------------
// kernel_launch
// ---------------------------------------------------------------------------
extern "C" void kernel_launch(void* const* d_in, const int* in_sizes, int n_in,
                              void* d_out, int out_size) {
    const float* x  = (const float*)d_in[0];
    const float* W1 = (const float*)d_in[1];
    const float* W2 = (const float*)d_in[2];
    const float* W3 = (const float*)d_in[3];
    float* out = (float*)d_out;

    __half *rh, *w12h, *w3h, *ea, *eb, *y_p;
    float *pa_p, *pb_p, *ss_p;
    cudaGetSymbolAddress((void**)&rh,   g_rh);
    cudaGetSymbolAddress((void**)&w12h, g_w12h);
    cudaGetSymbolAddress((void**)&w3h,  g_w3h);
    cudaGetSymbolAddress((void**)&ea,   g_ea);
    cudaGetSymbolAddress((void**)&eb,   g_eb);
    cudaGetSymbolAddress((void**)&y_p,  g_y);
    cudaGetSymbolAddress((void**)&pa_p, g_pa);
    cudaGetSymbolAddress((void**)&pb_p, g_pb);
    cudaGetSymbolAddress((void**)&ss_p, g_ss);

    cudaFuncSetAttribute(hgemm_exp_kernel, cudaFuncAttributeMaxDynamicSharedMemorySize,
                         SMEM2);
    cudaFuncSetAttribute(hgemm_scaled_kernel, cudaFuncAttributeMaxDynamicSharedMemorySize,
                         SMEM1);

    // Weight converts, one launch
    {
        int nv12 = (HID * EMB) / 4;
        int nv3  = (EMB * HID) / 4;
        int tot  = 2 * nv12 + nv3;
        wconv_all_kernel<<<(tot + 255) / 256, 256>>>(W1, W2, W3, w12h, w3h, nv12, nv3);
    }

    // 1) r = rmsnorm(x) -> fp16
    rmsnorm_f16_kernel<<<MROWS, 256>>>(x, rh, EMB);

    // 2) fused GEMM1/2 + exp + chunk sums (128x256 tiles, 512 thr)
    hgemm_exp_kernel<<<dim3((2 * HID) / 256, MROWS / 128), 512, SMEM2>>>(
        rh, w12h, ea, eb, pa_p, pb_p, MROWS, 2 * HID, EMB, HID);

    // 3) prefix over chunks, then within-chunk scan -> y fp16 + y^2 partials
    bar_pass2_kernel<<<(BATCH * HID) / 256, 256>>>(pa_p, pb_p);
    {
        dim3 grid(HID / 512, NCHUNK, BATCH);
        bar_pass3_kernel<<<grid, 256>>>(ea, eb, pa_p, pb_p, y_p, ss_p);
    }

    // 4) out = x + S[m] * (y @ W3^T), S from y^2 partials
    hgemm_scaled_kernel<<<dim3(EMB / 128, MROWS / 128), 256, SMEM1>>>(
        y_p, w3h, out, x, ss_p, MROWS, EMB, HID);
}

// round 15
// speedup vs baseline: 1.0926x; 1.0646x over previous
#include <cuda_runtime.h>
#include <cuda_bf16.h>
#include <cuda_fp16.h>
#include <cstdint>
#include <math.h>

// ---------------------------------------------------------------------------
// Problem constants
// ---------------------------------------------------------------------------
#define EMB   1024
#define HID   4096
#define BATCH 2
#define SEQT  4096
#define MROWS (BATCH * SEQT)   // 8192
#define EPS_F 1e-6f
#define NCHUNK 32
#define CHUNK  (SEQT / NCHUNK)   // 128  (== M-tile, chunk-aligned)

// ---------------------------------------------------------------------------
// Scratch buffers (static; runtime allocation forbidden)
// ---------------------------------------------------------------------------
__device__ __align__(16) __half g_rh  [(size_t)MROWS * EMB];          //  16 MB
__device__ __align__(16) __half g_w12h[(size_t)(2 * HID) * EMB];      //  16 MB
__device__ __align__(16) __half g_w3h [(size_t)EMB * HID];            //   8 MB
__device__ __align__(16) __half g_ea  [(size_t)MROWS * HID];          //  64 MB exp(a)
__device__ __align__(16) __half g_eb  [(size_t)MROWS * HID];          //  64 MB exp(b)
__device__ __align__(16) __half g_y   [(size_t)MROWS * HID];          //  64 MB y=(sa*sb)/t^2
__device__ __align__(16) float g_pa[(size_t)BATCH * NCHUNK * HID];    //   1 MB
__device__ __align__(16) float g_pb[(size_t)BATCH * NCHUNK * HID];    //   1 MB
__device__ __align__(16) float g_scale[MROWS];                        //  32 KB row scales

// ---------------------------------------------------------------------------
// PTX helpers (plain sm_103-legal)
// ---------------------------------------------------------------------------
__device__ __forceinline__ uint32_t smem_u32(const void* p) {
    uint32_t a;
    asm("{ .reg .u64 t; cvta.to.shared.u64 t, %1; cvt.u32.u64 %0, t; }"
        : "=r"(a) : "l"(p));
    return a;
}
__device__ __forceinline__ void cp16(uint32_t s, const void* g) {
    asm volatile("cp.async.cg.shared.global [%0], [%1], 16;" :: "r"(s), "l"(g));
}
__device__ __forceinline__ void cp_commit() {
    asm volatile("cp.async.commit_group;" ::: "memory");
}
__device__ __forceinline__ void ldsm_x4(uint32_t& r0, uint32_t& r1,
                                        uint32_t& r2, uint32_t& r3, uint32_t addr) {
    asm volatile("ldmatrix.sync.aligned.m8n8.x4.shared.b16 {%0,%1,%2,%3}, [%4];"
                 : "=r"(r0), "=r"(r1), "=r"(r2), "=r"(r3) : "r"(addr));
}
__device__ __forceinline__ void mma16(float& d0, float& d1, float& d2, float& d3,
                                      uint32_t a0, uint32_t a1, uint32_t a2, uint32_t a3,
                                      uint32_t b0, uint32_t b1) {
    asm volatile(
        "mma.sync.aligned.m16n8k16.row.col.f32.f16.f16.f32 "
        "{%0,%1,%2,%3}, {%4,%5,%6,%7}, {%8,%9}, {%0,%1,%2,%3};"
        : "+f"(d0), "+f"(d1), "+f"(d2), "+f"(d3)
        : "r"(a0), "r"(a1), "r"(a2), "r"(a3), "r"(b0), "r"(b1));
}
__device__ __forceinline__ uint32_t sw128(uint32_t off) {
    return off ^ ((off >> 3) & 0x70);
}

// ===========================================================================
// Shared GEMM config: 128x128x64 tiles, 256 threads (8 warps 2x4), 2 CTA/SM.
// ===========================================================================
#define BK 64
#define OPB 16384
#define STAGE_BYTES (2 * OPB)
#define NSTAGE 3
#define GEMM_SMEM (NSTAGE * STAGE_BYTES)

__device__ __forceinline__ void issue_tile_loads(
    uint32_t sbase, int st, const __half* Ab, const __half* Bb,
    int koff, int K, int tid)
{
    uint32_t stage = sbase + (uint32_t)st * STAGE_BYTES;
#pragma unroll
    for (int t = 0; t < 4; t++) {
        int idx = tid + t * 256;
        int row = idx >> 3;
        int u   = idx & 7;
        uint32_t sw = sw128((uint32_t)idx << 4);
        cp16(stage       + sw, Ab + (size_t)row * K + koff + u * 8);
        cp16(stage + OPB + sw, Bb + (size_t)row * K + koff + u * 8);
    }
}

// MODE 1: epilogue exp() -> fp16 E0/E1 + per-chunk column sums
// MODE 2: epilogue out = Cadd + S[m]*acc
template <int MODE>
__global__ void __launch_bounds__(256, 2)
hgemm_kernel(const __half* __restrict__ A, const __half* __restrict__ B,
             float* __restrict__ C0,
             const float* __restrict__ Cadd,
             __half* __restrict__ E0, __half* __restrict__ E1,
             float* __restrict__ pa, float* __restrict__ pb,
             const float* __restrict__ S,
             int M, int N, int K, int nsplit)
{
    extern __shared__ char smem[];
    uint32_t sbase = smem_u32(smem);
    const int tid  = threadIdx.x;
    const int wid  = tid >> 5;
    const int lane = tid & 31;
    const int wm   = wid & 1;
    const int wn   = wid >> 1;
    const int bm   = blockIdx.y * 128;
    const int bn   = blockIdx.x * 128;
    const int NC   = K / BK;

    const __half* Ab = A + (size_t)bm * K;
    const __half* Bb = B + (size_t)bn * K;

    float acc[4][4][4];
#pragma unroll
    for (int i = 0; i < 4; i++)
#pragma unroll
        for (int j = 0; j < 4; j++)
#pragma unroll
            for (int q = 0; q < 4; q++) acc[i][j][q] = 0.0f;

    const int a_m  = wm * 64 + (lane & 15);
    const int a_ku = lane >> 4;
    const int b_n  = wn * 32 + (lane & 7) + ((lane >> 4) << 3);
    const int b_ku = (lane >> 3) & 1;

    issue_tile_loads(sbase, 0, Ab, Bb, 0,  K, tid); cp_commit();
    issue_tile_loads(sbase, 1, Ab, Bb, BK, K, tid); cp_commit();

    for (int c = 0; c < NC; c++) {
        if (c + 1 < NC) asm volatile("cp.async.wait_group 1;" ::: "memory");
        else            asm volatile("cp.async.wait_group 0;" ::: "memory");
        __syncthreads();

        if (c + 2 < NC) {
            issue_tile_loads(sbase, (c + 2) % NSTAGE, Ab, Bb, (c + 2) * BK, K, tid);
            cp_commit();
        }

        uint32_t stage = sbase + (uint32_t)(c % NSTAGE) * STAGE_BYTES;
#pragma unroll
        for (int ks = 0; ks < 4; ks++) {
            uint32_t a0[4], a1[4], a2[4], a3[4];
            uint32_t bb0[2], bb1[2], bb2[2], bb3[2];
#pragma unroll
            for (int mf = 0; mf < 4; mf++) {
                int m  = a_m + mf * 16;
                int ku = ks * 2 + a_ku;
                ldsm_x4(a0[mf], a1[mf], a2[mf], a3[mf],
                        stage + sw128((uint32_t)(m * 128 + ku * 16)));
            }
#pragma unroll
            for (int nf2 = 0; nf2 < 2; nf2++) {
                int n  = b_n + nf2 * 16;
                int ku = ks * 2 + b_ku;
                uint32_t r0, r1, r2, r3;
                ldsm_x4(r0, r1, r2, r3,
                        stage + OPB + sw128((uint32_t)(n * 128 + ku * 16)));
                if (nf2 == 0) { bb0[0] = r0; bb0[1] = r1; bb1[0] = r2; bb1[1] = r3; }
                else          { bb2[0] = r0; bb2[1] = r1; bb3[0] = r2; bb3[1] = r3; }
            }
#pragma unroll
            for (int mf = 0; mf < 4; mf++) {
                mma16(acc[mf][0][0], acc[mf][0][1], acc[mf][0][2], acc[mf][0][3],
                      a0[mf], a1[mf], a2[mf], a3[mf], bb0[0], bb0[1]);
                mma16(acc[mf][1][0], acc[mf][1][1], acc[mf][1][2], acc[mf][1][3],
                      a0[mf], a1[mf], a2[mf], a3[mf], bb1[0], bb1[1]);
                mma16(acc[mf][2][0], acc[mf][2][1], acc[mf][2][2], acc[mf][2][3],
                      a0[mf], a1[mf], a2[mf], a3[mf], bb2[0], bb2[1]);
                mma16(acc[mf][3][0], acc[mf][3][1], acc[mf][3][2], acc[mf][3][3],
                      a0[mf], a1[mf], a2[mf], a3[mf], bb3[0], bb3[1]);
            }
        }
        __syncthreads();
    }

    const int inC0 = (bn < nsplit);
    const int ldc  = inC0 ? nsplit : (N - nsplit);
    const int cb   = inC0 ? bn : bn - nsplit;

    if (MODE == 2) {
#pragma unroll
        for (int mf = 0; mf < 4; mf++) {
            int r0 = bm + wm * 64 + mf * 16 + (lane >> 2);
            int r1 = r0 + 8;
            float s0 = S[r0], s1 = S[r1];
#pragma unroll
            for (int nf = 0; nf < 4; nf++) {
                int col = cb + wn * 32 + nf * 8 + (lane & 3) * 2;
                const float2 x0 = *(const float2*)(Cadd + (size_t)r0 * ldc + col);
                const float2 x1 = *(const float2*)(Cadd + (size_t)r1 * ldc + col);
                float2 v0 = make_float2(fmaf(s0, acc[mf][nf][0], x0.x),
                                        fmaf(s0, acc[mf][nf][1], x0.y));
                float2 v1 = make_float2(fmaf(s1, acc[mf][nf][2], x1.x),
                                        fmaf(s1, acc[mf][nf][3], x1.y));
                *(float2*)(C0 + (size_t)r0 * ldc + col) = v0;
                *(float2*)(C0 + (size_t)r1 * ldc + col) = v1;
            }
        }
    } else {
        // MODE 1: exp in place, store fp16, reduce per-chunk column sums
#pragma unroll
        for (int mf = 0; mf < 4; mf++)
#pragma unroll
            for (int nf = 0; nf < 4; nf++)
#pragma unroll
                for (int q = 0; q < 4; q++)
                    acc[mf][nf][q] = __expf(acc[mf][nf][q]);

        __half* Eb = inC0 ? E0 : E1;
#pragma unroll
        for (int mf = 0; mf < 4; mf++) {
            int r0 = bm + wm * 64 + mf * 16 + (lane >> 2);
            int r1 = r0 + 8;
#pragma unroll
            for (int nf = 0; nf < 4; nf++) {
                int col = cb + wn * 32 + nf * 8 + (lane & 3) * 2;
                *(__half2*)(Eb + (size_t)r0 * ldc + col) =
                    __floats2half2_rn(acc[mf][nf][0], acc[mf][nf][1]);
                *(__half2*)(Eb + (size_t)r1 * ldc + col) =
                    __floats2half2_rn(acc[mf][nf][2], acc[mf][nf][3]);
            }
        }

        float cs[4][2];
#pragma unroll
        for (int nf = 0; nf < 4; nf++) {
            cs[nf][0] = cs[nf][1] = 0.0f;
#pragma unroll
            for (int mf = 0; mf < 4; mf++) {
                cs[nf][0] += acc[mf][nf][0] + acc[mf][nf][2];
                cs[nf][1] += acc[mf][nf][1] + acc[mf][nf][3];
            }
#pragma unroll
            for (int off = 4; off < 32; off <<= 1) {
                cs[nf][0] += __shfl_xor_sync(0xffffffffu, cs[nf][0], off);
                cs[nf][1] += __shfl_xor_sync(0xffffffffu, cs[nf][1], off);
            }
        }
        float* red = (float*)smem;   // stages dead after final sync
        if (lane < 4) {
#pragma unroll
            for (int nf = 0; nf < 4; nf++) {
                int col = wn * 32 + nf * 8 + lane * 2;
                red[wm * 128 + col]     = cs[nf][0];
                red[wm * 128 + col + 1] = cs[nf][1];
            }
        }
        __syncthreads();
        if (tid < 128) {
            int bb = bm / SEQT;
            int ch = (bm % SEQT) / CHUNK;
            float* P = inC0 ? pa : pb;
            P[(size_t)(bb * NCHUNK + ch) * HID + cb + tid] =
                red[tid] + red[128 + tid];
        }
    }
}

// ---------------------------------------------------------------------------
// Block-wide sum reduce
// ---------------------------------------------------------------------------
__device__ __forceinline__ float block_reduce_sum(float v) {
    __shared__ float sh[32];
    int lane = threadIdx.x & 31;
    int wid  = threadIdx.x >> 5;
#pragma unroll
    for (int o = 16; o; o >>= 1) v += __shfl_xor_sync(0xffffffffu, v, o);
    if (lane == 0) sh[wid] = v;
    __syncthreads();
    int nw = blockDim.x >> 5;
    if (wid == 0) {
        v = (lane < nw) ? sh[lane] : 0.0f;
#pragma unroll
        for (int o = 16; o; o >>= 1) v += __shfl_xor_sync(0xffffffffu, v, o);
    }
    return v;
}

// ---------------------------------------------------------------------------
// RMSNorm fp32 -> fp16. One block per row.
// ---------------------------------------------------------------------------
__global__ void rmsnorm_f16_kernel(const float* __restrict__ in,
                                   __half* __restrict__ outp, int W) {
    int row = blockIdx.x;
    const float4* ir = (const float4*)(in + (size_t)row * W);
    int nvec = W >> 2;
    float ss = 0.0f;
    for (int i = threadIdx.x; i < nvec; i += 256) {
        float4 v = ir[i];
        ss += v.x * v.x + v.y * v.y + v.z * v.z + v.w * v.w;
    }
    ss = block_reduce_sum(ss);
    __shared__ float s_scale;
    if (threadIdx.x == 0) s_scale = rsqrtf(ss / (float)W + EPS_F);
    __syncthreads();
    float sc = s_scale;
    __half2* op = (__half2*)(outp + (size_t)row * W);
    for (int i = threadIdx.x; i < nvec; i += 256) {
        float4 v = ir[i];
        op[2 * i]     = __floats2half2_rn(v.x * sc, v.y * sc);
        op[2 * i + 1] = __floats2half2_rn(v.z * sc, v.w * sc);
    }
}

// ---------------------------------------------------------------------------
// Row rms-scale from fp16 y: scale[row] = rsqrt(mean(y^2) + eps)
// ---------------------------------------------------------------------------
__global__ void rowscale_kernel(const __half* __restrict__ y,
                                float* __restrict__ scale) {
    int row = blockIdx.x;
    const float4* ir = (const float4*)(y + (size_t)row * HID);  // 8 halves per ld
    float ss = 0.0f;
    for (int i = threadIdx.x; i < HID / 8; i += 256) {
        float4 u = ir[i];
        __half2 h0 = *(__half2*)&u.x, h1 = *(__half2*)&u.y;
        __half2 h2 = *(__half2*)&u.z, h3 = *(__half2*)&u.w;
        float2 v0 = __half22float2(h0), v1 = __half22float2(h1);
        float2 v2 = __half22float2(h2), v3 = __half22float2(h3);
        ss += v0.x * v0.x + v0.y * v0.y + v1.x * v1.x + v1.y * v1.y
            + v2.x * v2.x + v2.y * v2.y + v3.x * v3.x + v3.y * v3.y;
    }
    ss = block_reduce_sum(ss);
    if (threadIdx.x == 0) scale[row] = rsqrtf(ss / (float)HID + EPS_F);
}

// ---------------------------------------------------------------------------
// Fused fp32 -> fp16 convert for W1, W2, W3 in one launch.
// ---------------------------------------------------------------------------
__global__ void wconv_all_kernel(const float* __restrict__ W1,
                                 const float* __restrict__ W2,
                                 const float* __restrict__ W3,
                                 __half* __restrict__ w12h,
                                 __half* __restrict__ w3h,
                                 int nv12, int nv3) {
    int i = blockIdx.x * blockDim.x + threadIdx.x;
    const float* src;
    __half2* dst;
    int j;
    if (i < nv12)                { src = W1; dst = (__half2*)w12h;                      j = i; }
    else if (i < 2 * nv12)       { src = W2; dst = (__half2*)(w12h + (size_t)nv12 * 4); j = i - nv12; }
    else if (i < 2 * nv12 + nv3) { src = W3; dst = (__half2*)w3h;                      j = i - 2 * nv12; }
    else return;
    float4 v = ((const float4*)src)[j];
    dst[2 * j]     = __floats2half2_rn(v.x, v.y);
    dst[2 * j + 1] = __floats2half2_rn(v.z, v.w);
}

// ---------------------------------------------------------------------------
// pass2: exclusive prefix over chunk sums (batched loads for MLP)
// ---------------------------------------------------------------------------
__global__ void bar_pass2_kernel(float* __restrict__ pa,
                                 float* __restrict__ pb) {
    int idx = blockIdx.x * 256 + threadIdx.x;
    int bb = idx >> 12;
    int h  = idx & (HID - 1);
    float va[NCHUNK], vb[NCHUNK];
#pragma unroll
    for (int c = 0; c < NCHUNK; c++) {
        va[c] = pa[(size_t)(bb * NCHUNK + c) * HID + h];
        vb[c] = pb[(size_t)(bb * NCHUNK + c) * HID + h];
    }
    float ra = 0.0f, rb = 0.0f;
#pragma unroll
    for (int c = 0; c < NCHUNK; c++) {
        float ta = va[c], tb = vb[c];
        va[c] = ra; vb[c] = rb;
        ra += ta; rb += tb;
    }
#pragma unroll
    for (int c = 0; c < NCHUNK; c++) {
        pa[(size_t)(bb * NCHUNK + c) * HID + h] = va[c];
        pb[(size_t)(bb * NCHUNK + c) * HID + h] = vb[c];
    }
}

// ---------------------------------------------------------------------------
// pass3: within-chunk scan from prefix; y = (sa*sb)/(t+1)^2 in fp16.
// Pure streaming, no cross-thread reduction. 2 channels per thread.
// ---------------------------------------------------------------------------
__global__ void bar_pass3_kernel(const __half* __restrict__ ea,
                                 const __half* __restrict__ eb,
                                 const float* __restrict__ pa,
                                 const float* __restrict__ pb,
                                 __half* __restrict__ y) {
    int h2 = blockIdx.x * 256 + threadIdx.x;   // pair index
    int c  = blockIdx.y;
    int bb = blockIdx.z;
    size_t base = (size_t)bb * SEQT * HID + (size_t)c * CHUNK * HID + h2 * 2;
    const __half2* ap = (const __half2*)(ea + base);
    const __half2* bp = (const __half2*)(eb + base);
    __half2* yp = (__half2*)(y + base);

    int po = (bb * NCHUNK + c) * HID + h2 * 2;
    float sa0 = pa[po], sa1 = pa[po + 1];
    float sb0 = pb[po], sb1 = pb[po + 1];
#pragma unroll 4
    for (int t = 0; t < CHUNK; t++) {
        float2 va = __half22float2(ap[(size_t)t * (HID / 2)]);
        float2 vb = __half22float2(bp[(size_t)t * (HID / 2)]);
        sa0 += va.x; sa1 += va.y;
        sb0 += vb.x; sb1 += vb.y;
        float tf = (float)(c * CHUNK + t + 1);
        float inv = __fdividef(1.0f, tf * tf);
        yp[(size_t)t * (HID / 2)] =
            __floats2half2_rn(sa0 * sb0 * inv, sa1 * sb1 * inv);
    }
}

// ---------------------------------------------------------------------------
// kernel_launch
// ---------------------------------------------------------------------------
extern "C" void kernel_launch(void* const* d_in, const int* in_sizes, int n_in,
                              void* d_out, int out_size) {
    const float* x  = (const float*)d_in[0];
    const float* W1 = (const float*)d_in[1];
    const float* W2 = (const float*)d_in[2];
    const float* W3 = (const float*)d_in[3];
    float* out = (float*)d_out;

    __half *rh, *w12h, *w3h, *ea, *eb, *y_p;
    float *pa_p, *pb_p, *sc_p;
    cudaGetSymbolAddress((void**)&rh,   g_rh);
    cudaGetSymbolAddress((void**)&w12h, g_w12h);
    cudaGetSymbolAddress((void**)&w3h,  g_w3h);
    cudaGetSymbolAddress((void**)&ea,   g_ea);
    cudaGetSymbolAddress((void**)&eb,   g_eb);
    cudaGetSymbolAddress((void**)&y_p,  g_y);
    cudaGetSymbolAddress((void**)&pa_p, g_pa);
    cudaGetSymbolAddress((void**)&pb_p, g_pb);
    cudaGetSymbolAddress((void**)&sc_p, g_scale);

    cudaFuncSetAttribute(hgemm_kernel<1>, cudaFuncAttributeMaxDynamicSharedMemorySize,
                         GEMM_SMEM);
    cudaFuncSetAttribute(hgemm_kernel<2>, cudaFuncAttributeMaxDynamicSharedMemorySize,
                         GEMM_SMEM);

    // Weight converts, one launch
    {
        int nv12 = (HID * EMB) / 4;
        int nv3  = (EMB * HID) / 4;
        int tot  = 2 * nv12 + nv3;
        wconv_all_kernel<<<(tot + 255) / 256, 256>>>(W1, W2, W3, w12h, w3h, nv12, nv3);
    }

    // 1) r = rmsnorm(x) -> fp16
    rmsnorm_f16_kernel<<<MROWS, 256>>>(x, rh, EMB);

    // 2) fused GEMM1/2 + exp + chunk sums (128x128, 2 CTA/SM)
    hgemm_kernel<1><<<dim3((2 * HID) / 128, MROWS / 128), 256, GEMM_SMEM>>>(
        rh, w12h, nullptr, nullptr, ea, eb, pa_p, pb_p, nullptr,
        MROWS, 2 * HID, EMB, HID);

    // 3) prefix over chunks, then within-chunk streaming scan -> y fp16
    bar_pass2_kernel<<<(BATCH * HID) / 256, 256>>>(pa_p, pb_p);
    {
        dim3 grid(HID / 512, NCHUNK, BATCH);
        bar_pass3_kernel<<<grid, 256>>>(ea, eb, pa_p, pb_p, y_p);
    }

    // 4) per-row rms scales from y
    rowscale_kernel<<<MROWS, 256>>>(y_p, sc_p);

    // 5) out = x + S[m] * (y @ W3^T)
    hgemm_kernel<2><<<dim3(EMB / 128, MROWS / 128), 256, GEMM_SMEM>>>(
        y_p, w3h, out, x, nullptr, nullptr, nullptr, nullptr, sc_p,
        MROWS, EMB, HID, EMB);
}